// round 2
// baseline (speedup 1.0000x reference)
#include <cuda_runtime.h>
#include <math.h>

#define NN 50000
#define CC 128
#define EE 800000

// Scratch (device globals — no allocation allowed). Reused sequentially by the
// two relations; default-stream ordering guarantees correctness.
__device__ __align__(16) float g_msg[(size_t)NN * CC];
__device__ __align__(16) float g_aggr[(size_t)NN * CC];

__device__ __forceinline__ float sigm(float x) { return 1.0f / (1.0f + expf(-x)); }

// ---------------------------------------------------------------------------
// msg kernel: fused GEMM computing gates i (rows 0..127 of W_ih), g (256..383),
// o (384..511); epilogue applies the seq-len-1 LSTM cell:
//   c = sigmoid(i)*tanh(g);  msg = sigmoid(o)*tanh(c)
// Tiling: BM=64 nodes x BH=64 h-cols, 256 threads, 4x4 thread tile, 3 gate accs.
// ---------------------------------------------------------------------------
__global__ __launch_bounds__(256) void msg_kernel(const float* __restrict__ x,
                                                  const float* __restrict__ W,
                                                  const float* __restrict__ b,
                                                  int N)
{
    __shared__ float Xs[8][64];
    __shared__ float Wis[8][64];
    __shared__ float Wgs[8][64];
    __shared__ float Wos[8][64];

    const int tid = threadIdx.x;
    const int tx = tid & 15;       // col group
    const int ty = tid >> 4;       // row group
    const int rowBase = blockIdx.y * 64;
    const int colBase = blockIdx.x * 64;

    float ai[4][4], ag[4][4], ao[4][4];
#pragma unroll
    for (int i = 0; i < 4; ++i)
#pragma unroll
        for (int j = 0; j < 4; ++j) { ai[i][j] = 0.f; ag[i][j] = 0.f; ao[i][j] = 0.f; }

    for (int k0 = 0; k0 < 128; k0 += 8) {
#pragma unroll
        for (int t = tid; t < 512; t += 256) {
            const int kk = t >> 6;
            const int n = t & 63;
            const int gn = rowBase + n;
            Xs[kk][n] = (gn < N) ? x[(size_t)gn * 128 + k0 + kk] : 0.f;
            const int gh = colBase + n;   // < 128 always
            Wis[kk][n] = W[(size_t)gh * 128 + k0 + kk];
            Wgs[kk][n] = W[(size_t)(256 + gh) * 128 + k0 + kk];
            Wos[kk][n] = W[(size_t)(384 + gh) * 128 + k0 + kk];
        }
        __syncthreads();

#pragma unroll
        for (int kk = 0; kk < 8; ++kk) {
            const float4 xv  = *((const float4*)&Xs[kk][ty * 4]);
            const float4 wiv = *((const float4*)&Wis[kk][tx * 4]);
            const float4 wgv = *((const float4*)&Wgs[kk][tx * 4]);
            const float4 wov = *((const float4*)&Wos[kk][tx * 4]);
            const float xr[4]  = {xv.x, xv.y, xv.z, xv.w};
            const float wir[4] = {wiv.x, wiv.y, wiv.z, wiv.w};
            const float wgr[4] = {wgv.x, wgv.y, wgv.z, wgv.w};
            const float wor[4] = {wov.x, wov.y, wov.z, wov.w};
#pragma unroll
            for (int i = 0; i < 4; ++i)
#pragma unroll
                for (int j = 0; j < 4; ++j) {
                    ai[i][j] = fmaf(xr[i], wir[j], ai[i][j]);
                    ag[i][j] = fmaf(xr[i], wgr[j], ag[i][j]);
                    ao[i][j] = fmaf(xr[i], wor[j], ao[i][j]);
                }
        }
        __syncthreads();
    }

#pragma unroll
    for (int i = 0; i < 4; ++i) {
        const int gn = rowBase + ty * 4 + i;
        if (gn >= N) continue;
#pragma unroll
        for (int j = 0; j < 4; ++j) {
            const int gh = colBase + tx * 4 + j;
            const float gi = ai[i][j] + b[gh];
            const float gg = ag[i][j] + b[256 + gh];
            const float go = ao[i][j] + b[384 + gh];
            const float c = sigm(gi) * tanhf(gg);
            g_msg[(size_t)gn * 128 + gh] = sigm(go) * tanhf(c);
        }
    }
}

// ---------------------------------------------------------------------------
// zero aggr
// ---------------------------------------------------------------------------
__global__ __launch_bounds__(256) void zero_kernel()
{
    const int i = blockIdx.x * 256 + threadIdx.x;   // grid sized exactly NN*CC/4 threads
    ((float4*)g_aggr)[i] = make_float4(0.f, 0.f, 0.f, 0.f);
}

// ---------------------------------------------------------------------------
// scatter-add: one thread per (edge, 16B-chunk). float4 gather from g_msg,
// 4 scalar atomicAdd into g_aggr (addresses spread; L2-resident).
// ---------------------------------------------------------------------------
__global__ __launch_bounds__(256) void scatter_kernel(const int* __restrict__ edge)
{
    const int idx = blockIdx.x * 256 + threadIdx.x;   // grid sized exactly EE*32
    const int e = idx >> 5;
    const int lane = idx & 31;
    const int s = edge[e];
    const int d = edge[EE + e];
    const float4 v = ((const float4*)g_msg)[s * 32 + lane];
    float* a = &g_aggr[(size_t)d * 128 + lane * 4];
    atomicAdd(a + 0, v.x);
    atomicAdd(a + 1, v.y);
    atomicAdd(a + 2, v.z);
    atomicAdd(a + 3, v.w);
}

// ---------------------------------------------------------------------------
// out kernel: out[n,j] = relu(b[j] + sum_{k<256} A[n,k]*W_lin[j,k]),
// A[n,k] = k<128 ? x_dst[n,k] : aggr[n,k-128]. Same 64x64 tiling.
// ---------------------------------------------------------------------------
__global__ __launch_bounds__(256) void out_kernel(const float* __restrict__ x,
                                                  const float* __restrict__ Wl,
                                                  const float* __restrict__ bl,
                                                  float* __restrict__ out,
                                                  int N)
{
    __shared__ float As[8][64];
    __shared__ float Ws[8][64];

    const int tid = threadIdx.x;
    const int tx = tid & 15;
    const int ty = tid >> 4;
    const int rowBase = blockIdx.y * 64;
    const int colBase = blockIdx.x * 64;

    float acc[4][4];
#pragma unroll
    for (int i = 0; i < 4; ++i)
#pragma unroll
        for (int j = 0; j < 4; ++j) acc[i][j] = 0.f;

    for (int k0 = 0; k0 < 256; k0 += 8) {
#pragma unroll
        for (int t = tid; t < 512; t += 256) {
            const int kk = t >> 6;
            const int n = t & 63;
            const int gk = k0 + kk;
            const int gn = rowBase + n;
            float v = 0.f;
            if (gn < N) {
                v = (gk < 128) ? x[(size_t)gn * 128 + gk]
                               : g_aggr[(size_t)gn * 128 + (gk - 128)];
            }
            As[kk][n] = v;
            const int gj = colBase + n;   // < 128 always
            Ws[kk][n] = Wl[(size_t)gj * 256 + gk];
        }
        __syncthreads();

#pragma unroll
        for (int kk = 0; kk < 8; ++kk) {
            const float4 av = *((const float4*)&As[kk][ty * 4]);
            const float4 wv = *((const float4*)&Ws[kk][tx * 4]);
            const float ar[4] = {av.x, av.y, av.z, av.w};
            const float wr[4] = {wv.x, wv.y, wv.z, wv.w};
#pragma unroll
            for (int i = 0; i < 4; ++i)
#pragma unroll
                for (int j = 0; j < 4; ++j)
                    acc[i][j] = fmaf(ar[i], wr[j], acc[i][j]);
        }
        __syncthreads();
    }

#pragma unroll
    for (int i = 0; i < 4; ++i) {
        const int gn = rowBase + ty * 4 + i;
        if (gn >= N) continue;
#pragma unroll
        for (int j = 0; j < 4; ++j) {
            const int gj = colBase + tx * 4 + j;
            out[(size_t)gn * 128 + gj] = fmaxf(acc[i][j] + bl[gj], 0.f);
        }
    }
}

// ---------------------------------------------------------------------------
extern "C" void kernel_launch(void* const* d_in, const int* in_sizes, int n_in,
                              void* d_out, int out_size)
{
    const float* x_a      = (const float*)d_in[0];
    const float* x_b      = (const float*)d_in[1];
    const int*   edge_ab  = (const int*)d_in[2];
    const int*   edge_ba  = (const int*)d_in[3];
    const float* W_ih_ab  = (const float*)d_in[4];
    const float* b_ab     = (const float*)d_in[5];
    const float* W_lin_ab = (const float*)d_in[6];
    const float* b_lin_ab = (const float*)d_in[7];
    const float* W_ih_ba  = (const float*)d_in[8];
    const float* b_ba     = (const float*)d_in[9];
    const float* W_lin_ba = (const float*)d_in[10];
    const float* b_lin_ba = (const float*)d_in[11];
    float* out = (float*)d_out;

    const dim3 blk(256);
    const dim3 gG(2, (NN + 63) / 64);                 // 2 x 782 tiles
    const int zeroBlocks = (NN * CC / 4) / 256;       // 6250
    const int scatBlocks = (EE * 32) / 256;           // 100000

    // relation a_to_b: messages from x_a, aggregated at b-nodes -> out[1] = out_b
    msg_kernel<<<gG, blk>>>(x_a, W_ih_ab, b_ab, NN);
    zero_kernel<<<zeroBlocks, blk>>>();
    scatter_kernel<<<scatBlocks, blk>>>(edge_ab);
    out_kernel<<<gG, blk>>>(x_b, W_lin_ab, b_lin_ab, out + (size_t)NN * CC, NN);

    // relation b_to_a: messages from x_b, aggregated at a-nodes -> out[0] = out_a
    msg_kernel<<<gG, blk>>>(x_b, W_ih_ba, b_ba, NN);
    zero_kernel<<<zeroBlocks, blk>>>();
    scatter_kernel<<<scatBlocks, blk>>>(edge_ba);
    out_kernel<<<gG, blk>>>(x_a, W_lin_ba, b_lin_ba, out, NN);
}

// round 4
// speedup vs baseline: 3.2413x; 3.2413x over previous
#include <cuda_runtime.h>
#include <cuda_bf16.h>
#include <cstdint>
#include <math.h>

#define NN 50000
#define CC 128
#define EE 800000

// ---------------- scratch (static device globals; no allocation) -----------
__device__ __align__(16) float g_msg[(size_t)NN * CC];
__device__ __align__(16) float g_aggr[(size_t)NN * CC];
__device__ __align__(16) float g_gates[(size_t)NN * 384];   // [i | g | o]

__device__ __forceinline__ float sigm(float x) { return 1.0f / (1.0f + expf(-x)); }

// fp32 -> bf16 hi/lo split: x ~= hi + lo
__device__ __forceinline__ void cvt8(const float4 v0, const float4 v1, uint4& hi, uint4& lo) {
    const float f[8] = {v0.x, v0.y, v0.z, v0.w, v1.x, v1.y, v1.z, v1.w};
    uint32_t h[4], l[4];
#pragma unroll
    for (int p = 0; p < 4; ++p) {
        __nv_bfloat16 h0 = __float2bfloat16(f[2 * p]);
        __nv_bfloat16 h1 = __float2bfloat16(f[2 * p + 1]);
        __nv_bfloat16 l0 = __float2bfloat16(f[2 * p] - __bfloat162float(h0));
        __nv_bfloat16 l1 = __float2bfloat16(f[2 * p + 1] - __bfloat162float(h1));
        h[p] = (uint32_t)__bfloat16_as_ushort(h0) | ((uint32_t)__bfloat16_as_ushort(h1) << 16);
        l[p] = (uint32_t)__bfloat16_as_ushort(l0) | ((uint32_t)__bfloat16_as_ushort(l1) << 16);
    }
    hi = make_uint4(h[0], h[1], h[2], h[3]);
    lo = make_uint4(l[0], l[1], l[2], l[3]);
}

__device__ __forceinline__ void mma16816(float* d, const uint32_t* a, const uint32_t* b) {
    asm volatile(
        "mma.sync.aligned.m16n8k16.row.col.f32.bf16.bf16.f32 "
        "{%0,%1,%2,%3}, {%4,%5,%6,%7}, {%8,%9}, {%0,%1,%2,%3};"
        : "+f"(d[0]), "+f"(d[1]), "+f"(d[2]), "+f"(d[3])
        : "r"(a[0]), "r"(a[1]), "r"(a[2]), "r"(a[3]), "r"(b[0]), "r"(b[1]));
}

// ---------------------------------------------------------------------------
// HMMA GEMM: C[m, colOff+n] = sum_k Arow(m,k) * B[rowOff+n, k]
//   A rows: chunks < a1c from A1 (ld 128), rest from A2 (ld 128).
// CTA: 256 thr (8 warps, 4Mx2N), tile M=128 x N=64, K-chunk=32.
// mode 0: raw store (gates, grid.y in 0..5: gate*2+ntile). mode 1: bias+relu.
// SMEM rows padded to 40 bf16 -> conflict-free fragment LDS.
// ---------------------------------------------------------------------------
#define SA_STRIDE 40
__global__ __launch_bounds__(256, 2)
void gemm_kernel(const float* __restrict__ A1, const float* __restrict__ A2,
                 const float* __restrict__ B, const float* __restrict__ bias,
                 float* __restrict__ C,
                 int M, int ldB, int a1c, int nChunks, int ldC, int mode)
{
    __shared__ __nv_bfloat16 sAhi[128 * SA_STRIDE], sAlo[128 * SA_STRIDE];
    __shared__ __nv_bfloat16 sBhi[64 * SA_STRIDE],  sBlo[64 * SA_STRIDE];

    const int tid = threadIdx.x;
    const int wid = tid >> 5, lane = tid & 31;
    const int gq = lane >> 2, tg = lane & 3;          // group row / thread-in-group
    const int mW = (wid >> 1) * 32, nW = (wid & 1) * 32;
    const int mBase = blockIdx.x * 128;

    int rowOff, colOff;
    if (mode == 0) {
        const int gate = blockIdx.y >> 1, nt2 = blockIdx.y & 1;
        const int gr = (gate == 0) ? 0 : (gate == 1 ? 256 : 384);   // i, g, o
        rowOff = gr + nt2 * 64;
        colOff = gate * 128 + nt2 * 64;
    } else {
        rowOff = blockIdx.y * 64;
        colOff = blockIdx.y * 64;
    }

    float acc[2][4][4];
#pragma unroll
    for (int mt = 0; mt < 2; ++mt)
#pragma unroll
        for (int nt = 0; nt < 4; ++nt)
#pragma unroll
            for (int q = 0; q < 4; ++q) acc[mt][nt][q] = 0.f;

    for (int c = 0; c < nChunks; ++c) {
        // ---- stage A chunk: 128 rows x 32 cols ----
        {
            const float* Asrc = (c < a1c) ? A1 : A2;
            const int kcol = (c < a1c) ? c * 32 : (c - a1c) * 32;
            const int r = tid >> 1, half = (tid & 1) * 16;
            const int gn = mBase + r;
            float4 v0, v1, v2, v3;
            if (gn < M) {
                const float4* p = (const float4*)(Asrc + (size_t)gn * 128 + kcol + half);
                v0 = p[0]; v1 = p[1]; v2 = p[2]; v3 = p[3];
            } else {
                v0 = v1 = v2 = v3 = make_float4(0.f, 0.f, 0.f, 0.f);
            }
            uint4 h0, l0, h1, l1;
            cvt8(v0, v1, h0, l0);
            cvt8(v2, v3, h1, l1);
            const int off = r * SA_STRIDE + half;
            *(uint4*)&sAhi[off]     = h0;  *(uint4*)&sAhi[off + 8] = h1;
            *(uint4*)&sAlo[off]     = l0;  *(uint4*)&sAlo[off + 8] = l1;
        }
        // ---- stage B chunk: 64 rows x 32 cols ----
        {
            const int r = tid >> 2, q8 = (tid & 3) * 8;
            const float4* p = (const float4*)(B + (size_t)(rowOff + r) * ldB + c * 32 + q8);
            const float4 v0 = p[0], v1 = p[1];
            uint4 h, l;
            cvt8(v0, v1, h, l);
            const int off = r * SA_STRIDE + q8;
            *(uint4*)&sBhi[off] = h;
            *(uint4*)&sBlo[off] = l;
        }
        __syncthreads();

#pragma unroll
        for (int ks = 0; ks < 2; ++ks) {
            const int k16 = ks * 16;
            uint32_t ah[2][4], al[2][4], bh[4][2], bl[4][2];
#pragma unroll
            for (int mt = 0; mt < 2; ++mt) {
                const int base = (mW + mt * 16 + gq) * SA_STRIDE + k16 + tg * 2;
                ah[mt][0] = *(const uint32_t*)&sAhi[base];
                ah[mt][1] = *(const uint32_t*)&sAhi[base + 8 * SA_STRIDE];
                ah[mt][2] = *(const uint32_t*)&sAhi[base + 8];
                ah[mt][3] = *(const uint32_t*)&sAhi[base + 8 * SA_STRIDE + 8];
                al[mt][0] = *(const uint32_t*)&sAlo[base];
                al[mt][1] = *(const uint32_t*)&sAlo[base + 8 * SA_STRIDE];
                al[mt][2] = *(const uint32_t*)&sAlo[base + 8];
                al[mt][3] = *(const uint32_t*)&sAlo[base + 8 * SA_STRIDE + 8];
            }
#pragma unroll
            for (int nt = 0; nt < 4; ++nt) {
                const int base = (nW + nt * 8 + gq) * SA_STRIDE + k16 + tg * 2;
                bh[nt][0] = *(const uint32_t*)&sBhi[base];
                bh[nt][1] = *(const uint32_t*)&sBhi[base + 8];
                bl[nt][0] = *(const uint32_t*)&sBlo[base];
                bl[nt][1] = *(const uint32_t*)&sBlo[base + 8];
            }
#pragma unroll
            for (int mt = 0; mt < 2; ++mt)
#pragma unroll
                for (int nt = 0; nt < 4; ++nt) {
                    mma16816(acc[mt][nt], ah[mt], bh[nt]);
                    mma16816(acc[mt][nt], ah[mt], bl[nt]);
                    mma16816(acc[mt][nt], al[mt], bh[nt]);
                }
        }
        __syncthreads();
    }

    // ---- epilogue ----
#pragma unroll
    for (int mt = 0; mt < 2; ++mt)
#pragma unroll
        for (int nt = 0; nt < 4; ++nt) {
            const int r0 = mBase + mW + mt * 16 + gq;
            const int col = colOff + nW + nt * 8 + tg * 2;
            float2 v01 = make_float2(acc[mt][nt][0], acc[mt][nt][1]);
            float2 v23 = make_float2(acc[mt][nt][2], acc[mt][nt][3]);
            if (mode == 1) {
                const float b0 = bias[col], b1 = bias[col + 1];
                v01.x = fmaxf(v01.x + b0, 0.f);  v01.y = fmaxf(v01.y + b1, 0.f);
                v23.x = fmaxf(v23.x + b0, 0.f);  v23.y = fmaxf(v23.y + b1, 0.f);
            }
            if (r0 < M)     *(float2*)(C + (size_t)r0 * ldC + col) = v01;
            if (r0 + 8 < M) *(float2*)(C + (size_t)(r0 + 8) * ldC + col) = v23;
        }
}

// ---------------------------------------------------------------------------
// elementwise LSTM cell: msg = sigm(o+bo)*tanh(sigm(i+bi)*tanh(g+bg))
// ---------------------------------------------------------------------------
__global__ __launch_bounds__(256) void lstm_kernel(const float* __restrict__ b)
{
    const int idx4 = blockIdx.x * 256 + threadIdx.x;   // NN*32 threads
    const int n = idx4 >> 5;
    const int h = (idx4 & 31) * 4;
    const float4 gi = *(const float4*)&g_gates[(size_t)n * 384 + h];
    const float4 gg = *(const float4*)&g_gates[(size_t)n * 384 + 128 + h];
    const float4 go = *(const float4*)&g_gates[(size_t)n * 384 + 256 + h];
    const float4 bi = *(const float4*)&b[h];
    const float4 bg = *(const float4*)&b[256 + h];
    const float4 bo = *(const float4*)&b[384 + h];
    float4 m;
    m.x = sigm(go.x + bo.x) * tanhf(sigm(gi.x + bi.x) * tanhf(gg.x + bg.x));
    m.y = sigm(go.y + bo.y) * tanhf(sigm(gi.y + bi.y) * tanhf(gg.y + bg.y));
    m.z = sigm(go.z + bo.z) * tanhf(sigm(gi.z + bi.z) * tanhf(gg.z + bg.z));
    m.w = sigm(go.w + bo.w) * tanhf(sigm(gi.w + bi.w) * tanhf(gg.w + bg.w));
    *(float4*)&g_msg[(size_t)n * 128 + h] = m;
}

__global__ __launch_bounds__(256) void zero_kernel()
{
    const int i = blockIdx.x * 256 + threadIdx.x;
    ((float4*)g_aggr)[i] = make_float4(0.f, 0.f, 0.f, 0.f);
}

// scatter-add: one thread per (edge, 16B). Vector red (sm_90+, plain PTX).
__global__ __launch_bounds__(256) void scatter_kernel(const int* __restrict__ edge)
{
    const int idx = blockIdx.x * 256 + threadIdx.x;   // EE*32 threads
    const int e = idx >> 5;
    const int lane = idx & 31;
    const int s = edge[e];
    const int d = edge[EE + e];
    const float4 v = ((const float4*)g_msg)[s * 32 + lane];
    float* a = &g_aggr[(size_t)d * 128 + lane * 4];
    asm volatile("red.global.add.v4.f32 [%0], {%1,%2,%3,%4};"
                 :: "l"(a), "f"(v.x), "f"(v.y), "f"(v.z), "f"(v.w) : "memory");
}

// ---------------------------------------------------------------------------
extern "C" void kernel_launch(void* const* d_in, const int* in_sizes, int n_in,
                              void* d_out, int out_size)
{
    const float* x_a      = (const float*)d_in[0];
    const float* x_b      = (const float*)d_in[1];
    const int*   edge_ab  = (const int*)d_in[2];
    const int*   edge_ba  = (const int*)d_in[3];
    const float* W_ih_ab  = (const float*)d_in[4];
    const float* b_ab     = (const float*)d_in[5];
    const float* W_lin_ab = (const float*)d_in[6];
    const float* b_lin_ab = (const float*)d_in[7];
    const float* W_ih_ba  = (const float*)d_in[8];
    const float* b_ba     = (const float*)d_in[9];
    const float* W_lin_ba = (const float*)d_in[10];
    const float* b_lin_ba = (const float*)d_in[11];
    float* out = (float*)d_out;

    float* gates_ptr; cudaGetSymbolAddress((void**)&gates_ptr, g_gates);
    float* aggr_ptr;  cudaGetSymbolAddress((void**)&aggr_ptr, g_aggr);

    const int mTiles = (NN + 127) / 128;              // 391
    const dim3 gMsg(mTiles, 6), gOut(mTiles, 2), blk(256);
    const int zeroBlocks = (NN * CC / 4) / 256;       // 6250
    const int scatBlocks = (EE * 32) / 256;           // 100000
    const int lstmBlocks = (NN * 32) / 256;           // 6250

    // relation a_to_b: msgs from x_a -> aggregate at b -> out[1] = out_b
    gemm_kernel<<<gMsg, blk>>>(x_a, nullptr, W_ih_ab, nullptr, gates_ptr,
                               NN, 128, 4, 4, 384, 0);
    lstm_kernel<<<lstmBlocks, 256>>>(b_ab);
    zero_kernel<<<zeroBlocks, 256>>>();
    scatter_kernel<<<scatBlocks, 256>>>(edge_ab);
    gemm_kernel<<<gOut, blk>>>(x_b, aggr_ptr, W_lin_ab, b_lin_ab,
                               out + (size_t)NN * CC, NN, 256, 4, 8, 128, 1);

    // relation b_to_a: msgs from x_b -> aggregate at a -> out[0] = out_a
    gemm_kernel<<<gMsg, blk>>>(x_b, nullptr, W_ih_ba, nullptr, gates_ptr,
                               NN, 128, 4, 4, 384, 0);
    lstm_kernel<<<lstmBlocks, 256>>>(b_ba);
    zero_kernel<<<zeroBlocks, 256>>>();
    scatter_kernel<<<scatBlocks, 256>>>(edge_ba);
    gemm_kernel<<<gOut, blk>>>(x_a, aggr_ptr, W_lin_ba, b_lin_ba,
                               out, NN, 256, 4, 8, 128, 1);
}

// round 5
// speedup vs baseline: 3.3540x; 1.0348x over previous
#include <cuda_runtime.h>
#include <cuda_bf16.h>
#include <cstdint>
#include <math.h>

#define NN 50000
#define CC 128
#define EE 800000

// ---------------- scratch (static device globals; no allocation) -----------
__device__ __align__(16) float g_msg[(size_t)NN * CC];
__device__ __align__(16) float g_aggr[(size_t)NN * CC];
__device__ __align__(16) __nv_bfloat16 g_xah[(size_t)NN * CC], g_xal[(size_t)NN * CC];
__device__ __align__(16) __nv_bfloat16 g_xbh[(size_t)NN * CC], g_xbl[(size_t)NN * CC];
__device__ __align__(16) __nv_bfloat16 g_agh[(size_t)NN * CC], g_agl[(size_t)NN * CC];
__device__ __align__(16) __nv_bfloat16 g_wihh[2][512 * 128], g_wihl[2][512 * 128];
__device__ __align__(16) __nv_bfloat16 g_wlh[2][128 * 256], g_wll[2][128 * 256];

__device__ __forceinline__ float sigm(float x) { return 1.0f / (1.0f + expf(-x)); }

__device__ __forceinline__ void cvt8(const float4 v0, const float4 v1, uint4& hi, uint4& lo) {
    const float f[8] = {v0.x, v0.y, v0.z, v0.w, v1.x, v1.y, v1.z, v1.w};
    uint32_t h[4], l[4];
#pragma unroll
    for (int p = 0; p < 4; ++p) {
        __nv_bfloat16 h0 = __float2bfloat16(f[2 * p]);
        __nv_bfloat16 h1 = __float2bfloat16(f[2 * p + 1]);
        __nv_bfloat16 l0 = __float2bfloat16(f[2 * p] - __bfloat162float(h0));
        __nv_bfloat16 l1 = __float2bfloat16(f[2 * p + 1] - __bfloat162float(h1));
        h[p] = (uint32_t)__bfloat16_as_ushort(h0) | ((uint32_t)__bfloat16_as_ushort(h1) << 16);
        l[p] = (uint32_t)__bfloat16_as_ushort(l0) | ((uint32_t)__bfloat16_as_ushort(l1) << 16);
    }
    hi = make_uint4(h[0], h[1], h[2], h[3]);
    lo = make_uint4(l[0], l[1], l[2], l[3]);
}

__device__ __forceinline__ void mma16816(float* d, const uint32_t* a, const uint32_t* b) {
    asm volatile(
        "mma.sync.aligned.m16n8k16.row.col.f32.bf16.bf16.f32 "
        "{%0,%1,%2,%3}, {%4,%5,%6,%7}, {%8,%9}, {%0,%1,%2,%3};"
        : "+f"(d[0]), "+f"(d[1]), "+f"(d[2]), "+f"(d[3])
        : "r"(a[0]), "r"(a[1]), "r"(a[2]), "r"(a[3]), "r"(b[0]), "r"(b[1]));
}

__device__ __forceinline__ void cp16(uint32_t dst, const void* src) {
    asm volatile("cp.async.cg.shared.global [%0], [%1], 16;" :: "r"(dst), "l"(src));
}
#define CP_COMMIT() asm volatile("cp.async.commit_group;" ::: "memory")
#define CP_WAIT0()  asm volatile("cp.async.wait_group 0;" ::: "memory")
#define CP_WAIT1()  asm volatile("cp.async.wait_group 1;" ::: "memory")

#define STRD 40   // smem row stride in bf16 (32 data + 8 pad) -> conflict-free

// ---------------------------------------------------------------------------
// fp32 -> bf16 hi/lo converter. grid*256 threads, 8 floats each, exact size.
// ---------------------------------------------------------------------------
__global__ __launch_bounds__(256) void conv_kernel(const float* __restrict__ src,
                                                   __nv_bfloat16* __restrict__ h,
                                                   __nv_bfloat16* __restrict__ l)
{
    const int i = blockIdx.x * 256 + threadIdx.x;
    const float4 v0 = ((const float4*)src)[i * 2];
    const float4 v1 = ((const float4*)src)[i * 2 + 1];
    uint4 hi, lo;
    cvt8(v0, v1, hi, lo);
    ((uint4*)h)[i] = hi;
    ((uint4*)l)[i] = lo;
}

// ---------------------------------------------------------------------------
// msg GEMM (fused LSTM): per CTA 128 nodes x 64 h-cols, all 3 gates.
// grid (391, 2). A = x (bf16 hi/lo, ld128); B = W_ih (bf16 hi/lo, ld128).
// Double-buffered cp.async; epilogue: msg = sigm(o+bo)*tanh(sigm(i+bi)*tanh(g+bg))
// Stage layout (bf16 elems): A_hi 0, A_lo 5120, B_hi[g] 10240+g*2560,
// B_lo[g] 17920+g*2560; stage size 25600 elems (51200B), x2 stages.
// ---------------------------------------------------------------------------
__global__ __launch_bounds__(256, 1)
void msg_gemm(const __nv_bfloat16* __restrict__ Ah, const __nv_bfloat16* __restrict__ Al,
              const __nv_bfloat16* __restrict__ Bh, const __nv_bfloat16* __restrict__ Bl,
              const float* __restrict__ bias, float* __restrict__ Cmsg, int M)
{
    extern __shared__ __nv_bfloat16 dsm[];
    const uint32_t smemU = (uint32_t)__cvta_generic_to_shared(dsm);

    const int tid = threadIdx.x;
    const int wid = tid >> 5, lane = tid & 31;
    const int gq = lane >> 2, tg = lane & 3;
    const int mW = (wid >> 1) * 32, nW = (wid & 1) * 32;
    const int mBase = blockIdx.x * 128;
    const int colOff = blockIdx.y * 64;

    float acc[3][2][4][4];
#pragma unroll
    for (int g = 0; g < 3; ++g)
#pragma unroll
        for (int mt = 0; mt < 2; ++mt)
#pragma unroll
            for (int nt = 0; nt < 4; ++nt)
#pragma unroll
                for (int q = 0; q < 4; ++q) acc[g][mt][nt][q] = 0.f;

    // ---- staging issue for chunk c into stage s ----
    auto issue = [&](int c, int s) {
        const int kcol = c * 32;
        const uint32_t sB = smemU + s * 25600 * 2;
#pragma unroll
        for (int it = 0; it < 4; ++it) {                 // A: 1024 x 16B
            const int idx = it * 256 + tid;
            const int arr = idx >> 9;
            const int r = (idx >> 2) & 127;
            const int seg = idx & 3;
            int gn = mBase + r; if (gn > M - 1) gn = M - 1;   // clamp (rows discarded later)
            const __nv_bfloat16* src = (arr ? Al : Ah) + (size_t)gn * 128 + kcol + seg * 8;
            cp16(sB + (arr * 5120 + r * STRD + seg * 8) * 2, src);
        }
#pragma unroll
        for (int it = 0; it < 6; ++it) {                 // B: 3 gates x 512 x 16B
            const int idx = it * 256 + tid;
            const int arr = (idx >= 768) ? 1 : 0;
            const int rem = idx - arr * 768;
            const int g = rem >> 8;
            const int rr = (rem >> 2) & 63;
            const int seg = rem & 3;
            const int gr = (g == 0) ? 0 : (g == 1 ? 256 : 384);   // i, g, o
            const __nv_bfloat16* src = (arr ? Bl : Bh) + (size_t)(gr + colOff + rr) * 128 + kcol + seg * 8;
            cp16(sB + (10240 + arr * 7680 + g * 2560 + rr * STRD + seg * 8) * 2, src);
        }
        CP_COMMIT();
    };

    issue(0, 0);
    for (int c = 0; c < 4; ++c) {
        if (c + 1 < 4) { issue(c + 1, (c + 1) & 1); CP_WAIT1(); }
        else CP_WAIT0();
        __syncthreads();

        const __nv_bfloat16* st = dsm + (c & 1) * 25600;
        const __nv_bfloat16* pAh = st;
        const __nv_bfloat16* pAl = st + 5120;
#pragma unroll
        for (int ks = 0; ks < 2; ++ks) {
            const int k16 = ks * 16;
            uint32_t ah[2][4], al[2][4];
#pragma unroll
            for (int mt = 0; mt < 2; ++mt) {
                const int base = (mW + mt * 16 + gq) * STRD + k16 + tg * 2;
                ah[mt][0] = *(const uint32_t*)&pAh[base];
                ah[mt][1] = *(const uint32_t*)&pAh[base + 8 * STRD];
                ah[mt][2] = *(const uint32_t*)&pAh[base + 8];
                ah[mt][3] = *(const uint32_t*)&pAh[base + 8 * STRD + 8];
                al[mt][0] = *(const uint32_t*)&pAl[base];
                al[mt][1] = *(const uint32_t*)&pAl[base + 8 * STRD];
                al[mt][2] = *(const uint32_t*)&pAl[base + 8];
                al[mt][3] = *(const uint32_t*)&pAl[base + 8 * STRD + 8];
            }
#pragma unroll
            for (int g = 0; g < 3; ++g) {
                const __nv_bfloat16* pBh = st + 10240 + g * 2560;
                const __nv_bfloat16* pBl = st + 17920 + g * 2560;
                uint32_t bh[4][2], bl[4][2];
#pragma unroll
                for (int nt = 0; nt < 4; ++nt) {
                    const int base = (nW + nt * 8 + gq) * STRD + k16 + tg * 2;
                    bh[nt][0] = *(const uint32_t*)&pBh[base];
                    bh[nt][1] = *(const uint32_t*)&pBh[base + 8];
                    bl[nt][0] = *(const uint32_t*)&pBl[base];
                    bl[nt][1] = *(const uint32_t*)&pBl[base + 8];
                }
#pragma unroll
                for (int mt = 0; mt < 2; ++mt)
#pragma unroll
                    for (int nt = 0; nt < 4; ++nt) {
                        mma16816(acc[g][mt][nt], ah[mt], bh[nt]);
                        mma16816(acc[g][mt][nt], ah[mt], bl[nt]);
                        mma16816(acc[g][mt][nt], al[mt], bh[nt]);
                    }
            }
        }
        __syncthreads();
    }

    // ---- fused LSTM epilogue ----
#pragma unroll
    for (int mt = 0; mt < 2; ++mt)
#pragma unroll
        for (int nt = 0; nt < 4; ++nt) {
            const int r0 = mBase + mW + mt * 16 + gq;
            const int h = colOff + nW + nt * 8 + tg * 2;
            const float bi0 = bias[h],       bi1 = bias[h + 1];
            const float bg0 = bias[256 + h], bg1 = bias[256 + h + 1];
            const float bo0 = bias[384 + h], bo1 = bias[384 + h + 1];
            float m[4];
            m[0] = sigm(acc[2][mt][nt][0] + bo0) *
                   tanhf(sigm(acc[0][mt][nt][0] + bi0) * tanhf(acc[1][mt][nt][0] + bg0));
            m[1] = sigm(acc[2][mt][nt][1] + bo1) *
                   tanhf(sigm(acc[0][mt][nt][1] + bi1) * tanhf(acc[1][mt][nt][1] + bg1));
            m[2] = sigm(acc[2][mt][nt][2] + bo0) *
                   tanhf(sigm(acc[0][mt][nt][2] + bi0) * tanhf(acc[1][mt][nt][2] + bg0));
            m[3] = sigm(acc[2][mt][nt][3] + bo1) *
                   tanhf(sigm(acc[0][mt][nt][3] + bi1) * tanhf(acc[1][mt][nt][3] + bg1));
            if (r0 < M)     *(float2*)(Cmsg + (size_t)r0 * 128 + h) = make_float2(m[0], m[1]);
            if (r0 + 8 < M) *(float2*)(Cmsg + (size_t)(r0 + 8) * 128 + h) = make_float2(m[2], m[3]);
        }
}

// ---------------------------------------------------------------------------
// out GEMM: out[n,j] = relu(b[j] + sum_{k<256} A(n,k)*W_lin[j,k])
// A chunks 0-3 from x_dst, 4-7 from aggr (both bf16 hi/lo, ld128). grid (391,2).
// Stage: A_hi 0, A_lo 5120, B_hi 10240, B_lo 12800; 15360 elems x2 stages.
// ---------------------------------------------------------------------------
__global__ __launch_bounds__(256, 2)
void out_gemm(const __nv_bfloat16* __restrict__ Xh, const __nv_bfloat16* __restrict__ Xl,
              const __nv_bfloat16* __restrict__ Gh, const __nv_bfloat16* __restrict__ Gl,
              const __nv_bfloat16* __restrict__ Bh, const __nv_bfloat16* __restrict__ Bl,
              const float* __restrict__ bias, float* __restrict__ C, int M)
{
    extern __shared__ __nv_bfloat16 dsm[];
    const uint32_t smemU = (uint32_t)__cvta_generic_to_shared(dsm);

    const int tid = threadIdx.x;
    const int wid = tid >> 5, lane = tid & 31;
    const int gq = lane >> 2, tg = lane & 3;
    const int mW = (wid >> 1) * 32, nW = (wid & 1) * 32;
    const int mBase = blockIdx.x * 128;
    const int colOff = blockIdx.y * 64;

    float acc[2][4][4];
#pragma unroll
    for (int mt = 0; mt < 2; ++mt)
#pragma unroll
        for (int nt = 0; nt < 4; ++nt)
#pragma unroll
            for (int q = 0; q < 4; ++q) acc[mt][nt][q] = 0.f;

    auto issue = [&](int c, int s) {
        const int kcol = (c < 4 ? c : c - 4) * 32;
        const __nv_bfloat16* Ah = (c < 4) ? Xh : Gh;
        const __nv_bfloat16* Al = (c < 4) ? Xl : Gl;
        const uint32_t sB = smemU + s * 15360 * 2;
#pragma unroll
        for (int it = 0; it < 4; ++it) {                 // A: 1024 x 16B
            const int idx = it * 256 + tid;
            const int arr = idx >> 9;
            const int r = (idx >> 2) & 127;
            const int seg = idx & 3;
            int gn = mBase + r; if (gn > M - 1) gn = M - 1;
            const __nv_bfloat16* src = (arr ? Al : Ah) + (size_t)gn * 128 + kcol + seg * 8;
            cp16(sB + (arr * 5120 + r * STRD + seg * 8) * 2, src);
        }
#pragma unroll
        for (int it = 0; it < 2; ++it) {                 // B: 512 x 16B
            const int idx = it * 256 + tid;
            const int arr = idx >> 8;
            const int rr = (idx >> 2) & 63;
            const int seg = idx & 3;
            const __nv_bfloat16* src = (arr ? Bl : Bh) + (size_t)(colOff + rr) * 256 + c * 32 + seg * 8;
            cp16(sB + (10240 + arr * 2560 + rr * STRD + seg * 8) * 2, src);
        }
        CP_COMMIT();
    };

    issue(0, 0);
    for (int c = 0; c < 8; ++c) {
        if (c + 1 < 8) { issue(c + 1, (c + 1) & 1); CP_WAIT1(); }
        else CP_WAIT0();
        __syncthreads();

        const __nv_bfloat16* st = dsm + (c & 1) * 15360;
        const __nv_bfloat16* pAh = st;
        const __nv_bfloat16* pAl = st + 5120;
        const __nv_bfloat16* pBh = st + 10240;
        const __nv_bfloat16* pBl = st + 12800;
#pragma unroll
        for (int ks = 0; ks < 2; ++ks) {
            const int k16 = ks * 16;
            uint32_t ah[2][4], al[2][4], bh[4][2], bl[4][2];
#pragma unroll
            for (int mt = 0; mt < 2; ++mt) {
                const int base = (mW + mt * 16 + gq) * STRD + k16 + tg * 2;
                ah[mt][0] = *(const uint32_t*)&pAh[base];
                ah[mt][1] = *(const uint32_t*)&pAh[base + 8 * STRD];
                ah[mt][2] = *(const uint32_t*)&pAh[base + 8];
                ah[mt][3] = *(const uint32_t*)&pAh[base + 8 * STRD + 8];
                al[mt][0] = *(const uint32_t*)&pAl[base];
                al[mt][1] = *(const uint32_t*)&pAl[base + 8 * STRD];
                al[mt][2] = *(const uint32_t*)&pAl[base + 8];
                al[mt][3] = *(const uint32_t*)&pAl[base + 8 * STRD + 8];
            }
#pragma unroll
            for (int nt = 0; nt < 4; ++nt) {
                const int base = (nW + nt * 8 + gq) * STRD + k16 + tg * 2;
                bh[nt][0] = *(const uint32_t*)&pBh[base];
                bh[nt][1] = *(const uint32_t*)&pBh[base + 8];
                bl[nt][0] = *(const uint32_t*)&pBl[base];
                bl[nt][1] = *(const uint32_t*)&pBl[base + 8];
            }
#pragma unroll
            for (int mt = 0; mt < 2; ++mt)
#pragma unroll
                for (int nt = 0; nt < 4; ++nt) {
                    mma16816(acc[mt][nt], ah[mt], bh[nt]);
                    mma16816(acc[mt][nt], ah[mt], bl[nt]);
                    mma16816(acc[mt][nt], al[mt], bh[nt]);
                }
        }
        __syncthreads();
    }

#pragma unroll
    for (int mt = 0; mt < 2; ++mt)
#pragma unroll
        for (int nt = 0; nt < 4; ++nt) {
            const int r0 = mBase + mW + mt * 16 + gq;
            const int col = colOff + nW + nt * 8 + tg * 2;
            const float b0 = bias[col], b1 = bias[col + 1];
            float2 v01 = make_float2(fmaxf(acc[mt][nt][0] + b0, 0.f),
                                     fmaxf(acc[mt][nt][1] + b1, 0.f));
            float2 v23 = make_float2(fmaxf(acc[mt][nt][2] + b0, 0.f),
                                     fmaxf(acc[mt][nt][3] + b1, 0.f));
            if (r0 < M)     *(float2*)(C + (size_t)r0 * 128 + col) = v01;
            if (r0 + 8 < M) *(float2*)(C + (size_t)(r0 + 8) * 128 + col) = v23;
        }
}

__global__ __launch_bounds__(256) void zero_kernel()
{
    const int i = blockIdx.x * 256 + threadIdx.x;
    ((float4*)g_aggr)[i] = make_float4(0.f, 0.f, 0.f, 0.f);
}

__global__ __launch_bounds__(256) void scatter_kernel(const int* __restrict__ edge)
{
    const int idx = blockIdx.x * 256 + threadIdx.x;   // EE*32 threads
    const int e = idx >> 5;
    const int lane = idx & 31;
    const int s = edge[e];
    const int d = edge[EE + e];
    const float4 v = ((const float4*)g_msg)[s * 32 + lane];
    float* a = &g_aggr[(size_t)d * 128 + lane * 4];
    asm volatile("red.global.add.v4.f32 [%0], {%1,%2,%3,%4};"
                 :: "l"(a), "f"(v.x), "f"(v.y), "f"(v.z), "f"(v.w) : "memory");
}

// ---------------------------------------------------------------------------
extern "C" void kernel_launch(void* const* d_in, const int* in_sizes, int n_in,
                              void* d_out, int out_size)
{
    const float* x_a      = (const float*)d_in[0];
    const float* x_b      = (const float*)d_in[1];
    const int*   edge_ab  = (const int*)d_in[2];
    const int*   edge_ba  = (const int*)d_in[3];
    const float* W_ih_ab  = (const float*)d_in[4];
    const float* b_ab     = (const float*)d_in[5];
    const float* W_lin_ab = (const float*)d_in[6];
    const float* b_lin_ab = (const float*)d_in[7];
    const float* W_ih_ba  = (const float*)d_in[8];
    const float* b_ba     = (const float*)d_in[9];
    const float* W_lin_ba = (const float*)d_in[10];
    const float* b_lin_ba = (const float*)d_in[11];
    float* out = (float*)d_out;

    static const int SMEM_MSG = 102400, SMEM_OUT = 61440;
    cudaFuncSetAttribute(msg_gemm, cudaFuncAttributeMaxDynamicSharedMemorySize, SMEM_MSG);
    cudaFuncSetAttribute(out_gemm, cudaFuncAttributeMaxDynamicSharedMemorySize, SMEM_OUT);

    __nv_bfloat16 *xah, *xal, *xbh, *xbl, *agh, *agl, *wihh0, *wihl0, *wihh1, *wihl1,
                  *wlh0, *wll0, *wlh1, *wll1;
    float *msg_ptr, *aggr_ptr;
    cudaGetSymbolAddress((void**)&xah, g_xah);   cudaGetSymbolAddress((void**)&xal, g_xal);
    cudaGetSymbolAddress((void**)&xbh, g_xbh);   cudaGetSymbolAddress((void**)&xbl, g_xbl);
    cudaGetSymbolAddress((void**)&agh, g_agh);   cudaGetSymbolAddress((void**)&agl, g_agl);
    cudaGetSymbolAddress((void**)&msg_ptr, g_msg);
    cudaGetSymbolAddress((void**)&aggr_ptr, g_aggr);
    {
        __nv_bfloat16 (*p)[512 * 128];
        cudaGetSymbolAddress((void**)&p, g_wihh); wihh0 = p[0]; wihh1 = p[1];
        cudaGetSymbolAddress((void**)&p, g_wihl); wihl0 = p[0]; wihl1 = p[1];
    }
    {
        __nv_bfloat16 (*p)[128 * 256];
        cudaGetSymbolAddress((void**)&p, g_wlh); wlh0 = p[0]; wlh1 = p[1];
        cudaGetSymbolAddress((void**)&p, g_wll); wll0 = p[0]; wll1 = p[1];
    }

    const int mTiles = (NN + 127) / 128;              // 391
    const dim3 gG(mTiles, 2), blk(256);
    const int zeroBlocks = (NN * CC / 4) / 256;       // 6250
    const int scatBlocks = (EE * 32) / 256;           // 100000
    const int convX = (NN * CC / 8) / 256;            // 3125

    // --- pre-convert everything to bf16 hi/lo ---
    conv_kernel<<<convX, 256>>>(x_a, xah, xal);
    conv_kernel<<<convX, 256>>>(x_b, xbh, xbl);
    conv_kernel<<<32, 256>>>(W_ih_ab, wihh0, wihl0);
    conv_kernel<<<32, 256>>>(W_ih_ba, wihh1, wihl1);
    conv_kernel<<<16, 256>>>(W_lin_ab, wlh0, wll0);
    conv_kernel<<<16, 256>>>(W_lin_ba, wlh1, wll1);

    // relation a_to_b: msgs from x_a -> aggregate at b -> out[1] = out_b
    msg_gemm<<<gG, blk, SMEM_MSG>>>(xah, xal, wihh0, wihl0, b_ab, msg_ptr, NN);
    zero_kernel<<<zeroBlocks, 256>>>();
    scatter_kernel<<<scatBlocks, 256>>>(edge_ab);
    conv_kernel<<<convX, 256>>>(aggr_ptr, agh, agl);
    out_gemm<<<gG, blk, SMEM_OUT>>>(xbh, xbl, agh, agl, wlh0, wll0, b_lin_ab,
                                    out + (size_t)NN * CC, NN);

    // relation b_to_a: msgs from x_b -> aggregate at a -> out[0] = out_a
    msg_gemm<<<gG, blk, SMEM_MSG>>>(xbh, xbl, wihh1, wihl1, b_ba, msg_ptr, NN);
    zero_kernel<<<zeroBlocks, 256>>>();
    scatter_kernel<<<scatBlocks, 256>>>(edge_ba);
    conv_kernel<<<convX, 256>>>(aggr_ptr, agh, agl);
    out_gemm<<<gG, blk, SMEM_OUT>>>(xah, xal, agh, agl, wlh1, wll1, b_lin_ba,
                                    out, NN);
}

// round 6
// speedup vs baseline: 3.6126x; 1.0771x over previous
#include <cuda_runtime.h>
#include <cuda_bf16.h>
#include <cstdint>
#include <math.h>

#define NN 50000
#define CC 128
#define EE 800000

// ---------------- scratch (static device globals; no allocation) -----------
// Per-relation buffers (index 0 = a_to_b, 1 = b_to_a) so both branches run
// concurrently without aliasing.
__device__ __align__(16) float g_msg0[(size_t)NN * CC],  g_msg1[(size_t)NN * CC];
__device__ __align__(16) float g_aggr0[(size_t)NN * CC], g_aggr1[(size_t)NN * CC];
__device__ __align__(16) __nv_bfloat16 g_agh0[(size_t)NN * CC], g_agl0[(size_t)NN * CC];
__device__ __align__(16) __nv_bfloat16 g_agh1[(size_t)NN * CC], g_agl1[(size_t)NN * CC];
__device__ __align__(16) __nv_bfloat16 g_xah[(size_t)NN * CC], g_xal[(size_t)NN * CC];
__device__ __align__(16) __nv_bfloat16 g_xbh[(size_t)NN * CC], g_xbl[(size_t)NN * CC];
__device__ __align__(16) __nv_bfloat16 g_wihh[2][512 * 128], g_wihl[2][512 * 128];
__device__ __align__(16) __nv_bfloat16 g_wlh[2][128 * 256], g_wll[2][128 * 256];

__device__ __forceinline__ float sigm(float x) { return 1.0f / (1.0f + expf(-x)); }

__device__ __forceinline__ void cvt8(const float4 v0, const float4 v1, uint4& hi, uint4& lo) {
    const float f[8] = {v0.x, v0.y, v0.z, v0.w, v1.x, v1.y, v1.z, v1.w};
    uint32_t h[4], l[4];
#pragma unroll
    for (int p = 0; p < 4; ++p) {
        __nv_bfloat16 h0 = __float2bfloat16(f[2 * p]);
        __nv_bfloat16 h1 = __float2bfloat16(f[2 * p + 1]);
        __nv_bfloat16 l0 = __float2bfloat16(f[2 * p] - __bfloat162float(h0));
        __nv_bfloat16 l1 = __float2bfloat16(f[2 * p + 1] - __bfloat162float(h1));
        h[p] = (uint32_t)__bfloat16_as_ushort(h0) | ((uint32_t)__bfloat16_as_ushort(h1) << 16);
        l[p] = (uint32_t)__bfloat16_as_ushort(l0) | ((uint32_t)__bfloat16_as_ushort(l1) << 16);
    }
    hi = make_uint4(h[0], h[1], h[2], h[3]);
    lo = make_uint4(l[0], l[1], l[2], l[3]);
}

__device__ __forceinline__ void mma16816(float* d, const uint32_t* a, const uint32_t* b) {
    asm volatile(
        "mma.sync.aligned.m16n8k16.row.col.f32.bf16.bf16.f32 "
        "{%0,%1,%2,%3}, {%4,%5,%6,%7}, {%8,%9}, {%0,%1,%2,%3};"
        : "+f"(d[0]), "+f"(d[1]), "+f"(d[2]), "+f"(d[3])
        : "r"(a[0]), "r"(a[1]), "r"(a[2]), "r"(a[3]), "r"(b[0]), "r"(b[1]));
}

__device__ __forceinline__ void cp16(uint32_t dst, const void* src) {
    asm volatile("cp.async.cg.shared.global [%0], [%1], 16;" :: "r"(dst), "l"(src));
}
#define CP_COMMIT() asm volatile("cp.async.commit_group;" ::: "memory")
#define CP_WAIT0()  asm volatile("cp.async.wait_group 0;" ::: "memory")
#define CP_WAIT1()  asm volatile("cp.async.wait_group 1;" ::: "memory")

#define STRD 40   // smem row stride in bf16 (32 data + 8 pad) -> conflict-free

__global__ __launch_bounds__(256) void conv_kernel(const float* __restrict__ src,
                                                   __nv_bfloat16* __restrict__ h,
                                                   __nv_bfloat16* __restrict__ l)
{
    const int i = blockIdx.x * 256 + threadIdx.x;
    const float4 v0 = ((const float4*)src)[i * 2];
    const float4 v1 = ((const float4*)src)[i * 2 + 1];
    uint4 hi, lo;
    cvt8(v0, v1, hi, lo);
    ((uint4*)h)[i] = hi;
    ((uint4*)l)[i] = lo;
}

// ---------------------------------------------------------------------------
// msg GEMM (fused LSTM): per CTA 128 nodes x 64 h-cols, all 3 gates.
// ---------------------------------------------------------------------------
__global__ __launch_bounds__(256, 1)
void msg_gemm(const __nv_bfloat16* __restrict__ Ah, const __nv_bfloat16* __restrict__ Al,
              const __nv_bfloat16* __restrict__ Bh, const __nv_bfloat16* __restrict__ Bl,
              const float* __restrict__ bias, float* __restrict__ Cmsg, int M)
{
    extern __shared__ __nv_bfloat16 dsm[];
    const uint32_t smemU = (uint32_t)__cvta_generic_to_shared(dsm);

    const int tid = threadIdx.x;
    const int wid = tid >> 5, lane = tid & 31;
    const int gq = lane >> 2, tg = lane & 3;
    const int mW = (wid >> 1) * 32, nW = (wid & 1) * 32;
    const int mBase = blockIdx.x * 128;
    const int colOff = blockIdx.y * 64;

    float acc[3][2][4][4];
#pragma unroll
    for (int g = 0; g < 3; ++g)
#pragma unroll
        for (int mt = 0; mt < 2; ++mt)
#pragma unroll
            for (int nt = 0; nt < 4; ++nt)
#pragma unroll
                for (int q = 0; q < 4; ++q) acc[g][mt][nt][q] = 0.f;

    auto issue = [&](int c, int s) {
        const int kcol = c * 32;
        const uint32_t sB = smemU + s * 25600 * 2;
#pragma unroll
        for (int it = 0; it < 4; ++it) {                 // A: 1024 x 16B
            const int idx = it * 256 + tid;
            const int arr = idx >> 9;
            const int r = (idx >> 2) & 127;
            const int seg = idx & 3;
            int gn = mBase + r; if (gn > M - 1) gn = M - 1;
            const __nv_bfloat16* src = (arr ? Al : Ah) + (size_t)gn * 128 + kcol + seg * 8;
            cp16(sB + (arr * 5120 + r * STRD + seg * 8) * 2, src);
        }
#pragma unroll
        for (int it = 0; it < 6; ++it) {                 // B: 3 gates x 512 x 16B
            const int idx = it * 256 + tid;
            const int arr = (idx >= 768) ? 1 : 0;
            const int rem = idx - arr * 768;
            const int g = rem >> 8;
            const int rr = (rem >> 2) & 63;
            const int seg = rem & 3;
            const int gr = (g == 0) ? 0 : (g == 1 ? 256 : 384);   // i, g, o
            const __nv_bfloat16* src = (arr ? Bl : Bh) + (size_t)(gr + colOff + rr) * 128 + kcol + seg * 8;
            cp16(sB + (10240 + arr * 7680 + g * 2560 + rr * STRD + seg * 8) * 2, src);
        }
        CP_COMMIT();
    };

    issue(0, 0);
    for (int c = 0; c < 4; ++c) {
        if (c + 1 < 4) { issue(c + 1, (c + 1) & 1); CP_WAIT1(); }
        else CP_WAIT0();
        __syncthreads();

        const __nv_bfloat16* st = dsm + (c & 1) * 25600;
        const __nv_bfloat16* pAh = st;
        const __nv_bfloat16* pAl = st + 5120;
#pragma unroll
        for (int ks = 0; ks < 2; ++ks) {
            const int k16 = ks * 16;
            uint32_t ah[2][4], al[2][4];
#pragma unroll
            for (int mt = 0; mt < 2; ++mt) {
                const int base = (mW + mt * 16 + gq) * STRD + k16 + tg * 2;
                ah[mt][0] = *(const uint32_t*)&pAh[base];
                ah[mt][1] = *(const uint32_t*)&pAh[base + 8 * STRD];
                ah[mt][2] = *(const uint32_t*)&pAh[base + 8];
                ah[mt][3] = *(const uint32_t*)&pAh[base + 8 * STRD + 8];
                al[mt][0] = *(const uint32_t*)&pAl[base];
                al[mt][1] = *(const uint32_t*)&pAl[base + 8 * STRD];
                al[mt][2] = *(const uint32_t*)&pAl[base + 8];
                al[mt][3] = *(const uint32_t*)&pAl[base + 8 * STRD + 8];
            }
#pragma unroll
            for (int g = 0; g < 3; ++g) {
                const __nv_bfloat16* pBh = st + 10240 + g * 2560;
                const __nv_bfloat16* pBl = st + 17920 + g * 2560;
                uint32_t bh[4][2], bl[4][2];
#pragma unroll
                for (int nt = 0; nt < 4; ++nt) {
                    const int base = (nW + nt * 8 + gq) * STRD + k16 + tg * 2;
                    bh[nt][0] = *(const uint32_t*)&pBh[base];
                    bh[nt][1] = *(const uint32_t*)&pBh[base + 8];
                    bl[nt][0] = *(const uint32_t*)&pBl[base];
                    bl[nt][1] = *(const uint32_t*)&pBl[base + 8];
                }
#pragma unroll
                for (int mt = 0; mt < 2; ++mt)
#pragma unroll
                    for (int nt = 0; nt < 4; ++nt) {
                        mma16816(acc[g][mt][nt], ah[mt], bh[nt]);
                        mma16816(acc[g][mt][nt], ah[mt], bl[nt]);
                        mma16816(acc[g][mt][nt], al[mt], bh[nt]);
                    }
            }
        }
        __syncthreads();
    }

#pragma unroll
    for (int mt = 0; mt < 2; ++mt)
#pragma unroll
        for (int nt = 0; nt < 4; ++nt) {
            const int r0 = mBase + mW + mt * 16 + gq;
            const int h = colOff + nW + nt * 8 + tg * 2;
            const float bi0 = bias[h],       bi1 = bias[h + 1];
            const float bg0 = bias[256 + h], bg1 = bias[256 + h + 1];
            const float bo0 = bias[384 + h], bo1 = bias[384 + h + 1];
            float m[4];
            m[0] = sigm(acc[2][mt][nt][0] + bo0) *
                   tanhf(sigm(acc[0][mt][nt][0] + bi0) * tanhf(acc[1][mt][nt][0] + bg0));
            m[1] = sigm(acc[2][mt][nt][1] + bo1) *
                   tanhf(sigm(acc[0][mt][nt][1] + bi1) * tanhf(acc[1][mt][nt][1] + bg1));
            m[2] = sigm(acc[2][mt][nt][2] + bo0) *
                   tanhf(sigm(acc[0][mt][nt][2] + bi0) * tanhf(acc[1][mt][nt][2] + bg0));
            m[3] = sigm(acc[2][mt][nt][3] + bo1) *
                   tanhf(sigm(acc[0][mt][nt][3] + bi1) * tanhf(acc[1][mt][nt][3] + bg1));
            if (r0 < M)     *(float2*)(Cmsg + (size_t)r0 * 128 + h) = make_float2(m[0], m[1]);
            if (r0 + 8 < M) *(float2*)(Cmsg + (size_t)(r0 + 8) * 128 + h) = make_float2(m[2], m[3]);
        }
}

// ---------------------------------------------------------------------------
// out GEMM: out[n,j] = relu(b[j] + sum_{k<256} A(n,k)*W_lin[j,k])
// ---------------------------------------------------------------------------
__global__ __launch_bounds__(256, 2)
void out_gemm(const __nv_bfloat16* __restrict__ Xh, const __nv_bfloat16* __restrict__ Xl,
              const __nv_bfloat16* __restrict__ Gh, const __nv_bfloat16* __restrict__ Gl,
              const __nv_bfloat16* __restrict__ Bh, const __nv_bfloat16* __restrict__ Bl,
              const float* __restrict__ bias, float* __restrict__ C, int M)
{
    extern __shared__ __nv_bfloat16 dsm[];
    const uint32_t smemU = (uint32_t)__cvta_generic_to_shared(dsm);

    const int tid = threadIdx.x;
    const int wid = tid >> 5, lane = tid & 31;
    const int gq = lane >> 2, tg = lane & 3;
    const int mW = (wid >> 1) * 32, nW = (wid & 1) * 32;
    const int mBase = blockIdx.x * 128;
    const int colOff = blockIdx.y * 64;

    float acc[2][4][4];
#pragma unroll
    for (int mt = 0; mt < 2; ++mt)
#pragma unroll
        for (int nt = 0; nt < 4; ++nt)
#pragma unroll
            for (int q = 0; q < 4; ++q) acc[mt][nt][q] = 0.f;

    auto issue = [&](int c, int s) {
        const int kcol = (c < 4 ? c : c - 4) * 32;
        const __nv_bfloat16* Ah = (c < 4) ? Xh : Gh;
        const __nv_bfloat16* Al = (c < 4) ? Xl : Gl;
        const uint32_t sB = smemU + s * 15360 * 2;
#pragma unroll
        for (int it = 0; it < 4; ++it) {
            const int idx = it * 256 + tid;
            const int arr = idx >> 9;
            const int r = (idx >> 2) & 127;
            const int seg = idx & 3;
            int gn = mBase + r; if (gn > M - 1) gn = M - 1;
            const __nv_bfloat16* src = (arr ? Al : Ah) + (size_t)gn * 128 + kcol + seg * 8;
            cp16(sB + (arr * 5120 + r * STRD + seg * 8) * 2, src);
        }
#pragma unroll
        for (int it = 0; it < 2; ++it) {
            const int idx = it * 256 + tid;
            const int arr = idx >> 8;
            const int rr = (idx >> 2) & 63;
            const int seg = idx & 3;
            const __nv_bfloat16* src = (arr ? Bl : Bh) + (size_t)(colOff + rr) * 256 + c * 32 + seg * 8;
            cp16(sB + (10240 + arr * 2560 + rr * STRD + seg * 8) * 2, src);
        }
        CP_COMMIT();
    };

    issue(0, 0);
    for (int c = 0; c < 8; ++c) {
        if (c + 1 < 8) { issue(c + 1, (c + 1) & 1); CP_WAIT1(); }
        else CP_WAIT0();
        __syncthreads();

        const __nv_bfloat16* st = dsm + (c & 1) * 15360;
        const __nv_bfloat16* pAh = st;
        const __nv_bfloat16* pAl = st + 5120;
        const __nv_bfloat16* pBh = st + 10240;
        const __nv_bfloat16* pBl = st + 12800;
#pragma unroll
        for (int ks = 0; ks < 2; ++ks) {
            const int k16 = ks * 16;
            uint32_t ah[2][4], al[2][4], bh[4][2], bl[4][2];
#pragma unroll
            for (int mt = 0; mt < 2; ++mt) {
                const int base = (mW + mt * 16 + gq) * STRD + k16 + tg * 2;
                ah[mt][0] = *(const uint32_t*)&pAh[base];
                ah[mt][1] = *(const uint32_t*)&pAh[base + 8 * STRD];
                ah[mt][2] = *(const uint32_t*)&pAh[base + 8];
                ah[mt][3] = *(const uint32_t*)&pAh[base + 8 * STRD + 8];
                al[mt][0] = *(const uint32_t*)&pAl[base];
                al[mt][1] = *(const uint32_t*)&pAl[base + 8 * STRD];
                al[mt][2] = *(const uint32_t*)&pAl[base + 8];
                al[mt][3] = *(const uint32_t*)&pAl[base + 8 * STRD + 8];
            }
#pragma unroll
            for (int nt = 0; nt < 4; ++nt) {
                const int base = (nW + nt * 8 + gq) * STRD + k16 + tg * 2;
                bh[nt][0] = *(const uint32_t*)&pBh[base];
                bh[nt][1] = *(const uint32_t*)&pBh[base + 8];
                bl[nt][0] = *(const uint32_t*)&pBl[base];
                bl[nt][1] = *(const uint32_t*)&pBl[base + 8];
            }
#pragma unroll
            for (int mt = 0; mt < 2; ++mt)
#pragma unroll
                for (int nt = 0; nt < 4; ++nt) {
                    mma16816(acc[mt][nt], ah[mt], bh[nt]);
                    mma16816(acc[mt][nt], ah[mt], bl[nt]);
                    mma16816(acc[mt][nt], al[mt], bh[nt]);
                }
        }
        __syncthreads();
    }

#pragma unroll
    for (int mt = 0; mt < 2; ++mt)
#pragma unroll
        for (int nt = 0; nt < 4; ++nt) {
            const int r0 = mBase + mW + mt * 16 + gq;
            const int col = colOff + nW + nt * 8 + tg * 2;
            const float b0 = bias[col], b1 = bias[col + 1];
            float2 v01 = make_float2(fmaxf(acc[mt][nt][0] + b0, 0.f),
                                     fmaxf(acc[mt][nt][1] + b1, 0.f));
            float2 v23 = make_float2(fmaxf(acc[mt][nt][2] + b0, 0.f),
                                     fmaxf(acc[mt][nt][3] + b1, 0.f));
            if (r0 < M)     *(float2*)(C + (size_t)r0 * 128 + col) = v01;
            if (r0 + 8 < M) *(float2*)(C + (size_t)(r0 + 8) * 128 + col) = v23;
        }
}

__global__ __launch_bounds__(256) void zero_kernel(float* __restrict__ buf)
{
    const int i = blockIdx.x * 256 + threadIdx.x;
    ((float4*)buf)[i] = make_float4(0.f, 0.f, 0.f, 0.f);
}

__global__ __launch_bounds__(256) void scatter_kernel(const int* __restrict__ edge,
                                                      const float* __restrict__ msg,
                                                      float* __restrict__ aggr)
{
    const int idx = blockIdx.x * 256 + threadIdx.x;   // EE*32 threads
    const int e = idx >> 5;
    const int lane = idx & 31;
    const int s = edge[e];
    const int d = edge[EE + e];
    const float4 v = ((const float4*)msg)[s * 32 + lane];
    float* a = &aggr[(size_t)d * 128 + lane * 4];
    asm volatile("red.global.add.v4.f32 [%0], {%1,%2,%3,%4};"
                 :: "l"(a), "f"(v.x), "f"(v.y), "f"(v.z), "f"(v.w) : "memory");
}

// ---------------------------------------------------------------------------
extern "C" void kernel_launch(void* const* d_in, const int* in_sizes, int n_in,
                              void* d_out, int out_size)
{
    const float* x_a      = (const float*)d_in[0];
    const float* x_b      = (const float*)d_in[1];
    const int*   edge_ab  = (const int*)d_in[2];
    const int*   edge_ba  = (const int*)d_in[3];
    const float* W_ih_ab  = (const float*)d_in[4];
    const float* b_ab     = (const float*)d_in[5];
    const float* W_lin_ab = (const float*)d_in[6];
    const float* b_lin_ab = (const float*)d_in[7];
    const float* W_ih_ba  = (const float*)d_in[8];
    const float* b_ba     = (const float*)d_in[9];
    const float* W_lin_ba = (const float*)d_in[10];
    const float* b_lin_ba = (const float*)d_in[11];
    float* out = (float*)d_out;

    static const int SMEM_MSG = 102400, SMEM_OUT = 61440;
    cudaFuncSetAttribute(msg_gemm, cudaFuncAttributeMaxDynamicSharedMemorySize, SMEM_MSG);
    cudaFuncSetAttribute(out_gemm, cudaFuncAttributeMaxDynamicSharedMemorySize, SMEM_OUT);

    __nv_bfloat16 *xah, *xal, *xbh, *xbl;
    __nv_bfloat16 *agh0, *agl0, *agh1, *agl1;
    __nv_bfloat16 *wihh0, *wihl0, *wihh1, *wihl1, *wlh0, *wll0, *wlh1, *wll1;
    float *msg0, *msg1, *aggr0, *aggr1;
    cudaGetSymbolAddress((void**)&xah, g_xah);   cudaGetSymbolAddress((void**)&xal, g_xal);
    cudaGetSymbolAddress((void**)&xbh, g_xbh);   cudaGetSymbolAddress((void**)&xbl, g_xbl);
    cudaGetSymbolAddress((void**)&agh0, g_agh0); cudaGetSymbolAddress((void**)&agl0, g_agl0);
    cudaGetSymbolAddress((void**)&agh1, g_agh1); cudaGetSymbolAddress((void**)&agl1, g_agl1);
    cudaGetSymbolAddress((void**)&msg0, g_msg0); cudaGetSymbolAddress((void**)&msg1, g_msg1);
    cudaGetSymbolAddress((void**)&aggr0, g_aggr0); cudaGetSymbolAddress((void**)&aggr1, g_aggr1);
    {
        __nv_bfloat16 (*p)[512 * 128];
        cudaGetSymbolAddress((void**)&p, g_wihh); wihh0 = p[0]; wihh1 = p[1];
        cudaGetSymbolAddress((void**)&p, g_wihl); wihl0 = p[0]; wihl1 = p[1];
    }
    {
        __nv_bfloat16 (*p)[128 * 256];
        cudaGetSymbolAddress((void**)&p, g_wlh); wlh0 = p[0]; wlh1 = p[1];
        cudaGetSymbolAddress((void**)&p, g_wll); wll0 = p[0]; wll1 = p[1];
    }

    const int mTiles = (NN + 127) / 128;              // 391
    const dim3 gG(mTiles, 2), blk(256);
    const int zeroBlocks = (NN * CC / 4) / 256;       // 6250
    const int scatBlocks = (EE * 32) / 256;           // 100000
    const int convX = (NN * CC / 8) / 256;            // 3125

    cudaStream_t s2;
    cudaEvent_t eFork, eJoin;
    cudaStreamCreateWithFlags(&s2, cudaStreamNonBlocking);
    cudaEventCreateWithFlags(&eFork, cudaEventDisableTiming);
    cudaEventCreateWithFlags(&eJoin, cudaEventDisableTiming);

    // --- shared prologue on captured default stream ---
    conv_kernel<<<convX, 256>>>(x_a, xah, xal);
    conv_kernel<<<convX, 256>>>(x_b, xbh, xbl);
    conv_kernel<<<32, 256>>>(W_ih_ab, wihh0, wihl0);
    conv_kernel<<<32, 256>>>(W_ih_ba, wihh1, wihl1);
    conv_kernel<<<16, 256>>>(W_lin_ab, wlh0, wll0);
    conv_kernel<<<16, 256>>>(W_lin_ba, wlh1, wll1);
    zero_kernel<<<zeroBlocks, 256>>>(aggr0);
    zero_kernel<<<zeroBlocks, 256>>>(aggr1);

    // --- fork ---
    cudaEventRecord(eFork, 0);
    cudaStreamWaitEvent(s2, eFork, 0);

    // branch 0 (default stream): relation a_to_b -> out[1] = out_b
    msg_gemm<<<gG, blk, SMEM_MSG>>>(xah, xal, wihh0, wihl0, b_ab, msg0, NN);
    scatter_kernel<<<scatBlocks, 256>>>(edge_ab, msg0, aggr0);
    conv_kernel<<<convX, 256>>>(aggr0, agh0, agl0);
    out_gemm<<<gG, blk, SMEM_OUT>>>(xbh, xbl, agh0, agl0, wlh0, wll0, b_lin_ab,
                                    out + (size_t)NN * CC, NN);

    // branch 1 (s2): relation b_to_a -> out[0] = out_a
    msg_gemm<<<gG, blk, SMEM_MSG, s2>>>(xbh, xbl, wihh1, wihl1, b_ba, msg1, NN);
    scatter_kernel<<<scatBlocks, 256, 0, s2>>>(edge_ba, msg1, aggr1);
    conv_kernel<<<convX, 256, 0, s2>>>(aggr1, agh1, agl1);
    out_gemm<<<gG, blk, SMEM_OUT, s2>>>(xah, xal, agh1, agl1, wlh1, wll1, b_lin_ba,
                                        out, NN);

    // --- join ---
    cudaEventRecord(eJoin, s2);
    cudaStreamWaitEvent(0, eJoin, 0);

    cudaEventDestroy(eFork);
    cudaEventDestroy(eJoin);
    cudaStreamDestroy(s2);
}